// round 8
// baseline (speedup 1.0000x reference)
#include <cuda_runtime.h>
#include <cuda_fp16.h>
#include <cstdint>

#define N_SAMP 4096
#define Fh 15
#define Wd 120
#define NWIN 12
#define Sw 10
#define Pn 105
#define HPR 270
#define K1 43200
#define KI 38400        // int8 (bounded) k region
#define KF 4800         // fp16 (unbounded) k region
#define N1 512
#define NTI 300         // int8 stages, BK=128 bytes
#define NTF 75          // fp16 stages, BK=64 halves
#define STAGES 3

// ---------------- device-global scratch (no allocations anywhere) ----------
__device__ char  g_Ai1[(size_t)N_SAMP * KI];   // 157 MB
__device__ char  g_Ai2[(size_t)N_SAMP * KI];   // 157 MB
__device__ __half g_Af1[(size_t)N_SAMP * KF];  // 39 MB
__device__ __half g_Af2[(size_t)N_SAMP * KF];  // 39 MB
__device__ char  g_Wi1[(size_t)N1 * KI];
__device__ char  g_Wi2[(size_t)N1 * KI];
__device__ __half g_Wf1[(size_t)N1 * KF];
__device__ __half g_Wf2[(size_t)N1 * KF];
__device__ float g_Wscale[N1];
__device__ float g_y1[(size_t)N_SAMP * N1];

// ---------------- helpers ---------------------------------------------------
__device__ __forceinline__ float ffill(float x) {
    unsigned u = __float_as_uint(x);
    return ((u & 0x7f800000u) == 0x7f800000u) ? 0.0f : x;
}
__device__ __forceinline__ uint32_t smem_u32(const void* p) {
    uint32_t a;
    asm("{ .reg .u64 t; cvta.to.shared.u64 t, %1; cvt.u32.u64 %0, t; }" : "=r"(a) : "l"(p));
    return a;
}
#define SWZ(o) ((o) ^ (((o) >> 3) & 0x70))

__device__ __forceinline__ void ldsm4(uint32_t* r, uint32_t addr) {
    asm volatile("ldmatrix.sync.aligned.m8n8.x4.shared.b16 {%0,%1,%2,%3}, [%4];"
                 : "=r"(r[0]), "=r"(r[1]), "=r"(r[2]), "=r"(r[3]) : "r"(addr));
}
__device__ __forceinline__ void hmma_f32(float* d, const uint32_t* a, const uint32_t* b) {
    asm volatile(
        "mma.sync.aligned.m16n8k16.row.col.f32.f16.f16.f32 "
        "{%0,%1,%2,%3},{%4,%5,%6,%7},{%8,%9},{%0,%1,%2,%3};"
        : "+f"(d[0]), "+f"(d[1]), "+f"(d[2]), "+f"(d[3])
        : "r"(a[0]), "r"(a[1]), "r"(a[2]), "r"(a[3]), "r"(b[0]), "r"(b[1]));
}
__device__ __forceinline__ void hmma_f16(uint32_t* d, const uint32_t* a, const uint32_t* b) {
    asm volatile(
        "mma.sync.aligned.m16n8k16.row.col.f16.f16.f16.f16 "
        "{%0,%1},{%2,%3,%4,%5},{%6,%7},{%0,%1};"
        : "+r"(d[0]), "+r"(d[1])
        : "r"(a[0]), "r"(a[1]), "r"(a[2]), "r"(a[3]), "r"(b[0]), "r"(b[1]));
}
__device__ __forceinline__ void mma_s8(int* d, const uint32_t* a, const uint32_t* b) {
    asm volatile(
        "mma.sync.aligned.m16n8k32.row.col.s32.s8.s8.s32 "
        "{%0,%1,%2,%3},{%4,%5,%6,%7},{%8,%9},{%0,%1,%2,%3};"
        : "+r"(d[0]), "+r"(d[1]), "+r"(d[2]), "+r"(d[3])
        : "r"(a[0]), "r"(a[1]), "r"(a[2]), "r"(a[3]), "r"(b[0]), "r"(b[1]));
}
__device__ __forceinline__ int iclamp(int v, int lo, int hi) {
    return v < lo ? lo : (v > hi ? hi : v);
}

// Deterministic global int8 A-scale from scalar params (same result everywhere).
__device__ float compute_sA(const float* gm, const float* bt, const float* mn,
                            const float* vr, const float* cw, const float* cb) {
    float bsc = rsqrtf(vr[0] + 1e-5f) * gm[0];
    float bsh = bt[0] - mn[0] * bsc;
    float B = fabsf(bsc) * 1.15f + fabsf(bsh);
    float mx = 0.f;
    for (int o = 0; o < 16; o++) {
        float s = (fabsf(cw[3 * o]) + fabsf(cw[3 * o + 1]) + fabsf(cw[3 * o + 2])) * B
                + fabsf(cb[o]);
        mx = fmaxf(mx, s);
    }
    return mx * (1.0f / 127.0f);
}

// h -> bounded? and permuted position
// bounded: h in [0,225) -> pos=h ; h in [255,270) -> pos=h-30  (pos 0..239)
// unbounded: h in [225,255) -> fpos=h-225 (0..29)

// ============================================================================
// Kernel 1 (fused): blocks [0,4096) = features -> quantized A planes
//                   blocks [4096,4608) = fc1 weight split (block per out-row)
// ============================================================================
__global__ __launch_bounds__(256) void feat_kernel(
    const float* __restrict__ data,
    const float* __restrict__ bn_gamma, const float* __restrict__ bn_beta,
    const float* __restrict__ bn_mean, const float* __restrict__ bn_var,
    const float* __restrict__ conv_w, const float* __restrict__ conv_b,
    const float* __restrict__ fc1_w)
{
    const int tid = threadIdx.x;

    if (blockIdx.x >= N_SAMP) {
        // ---- weight split: one block per output row n ----
        __shared__ float red[256];
        const int n = blockIdx.x - N_SAMP;
        const float* wr = fc1_w + (size_t)n * K1;
        float m = 0.f;
        for (int k = tid; k < K1; k += 256) {
            const int r = k % 2700;
            const int h = r / 10;
            if (h < 225 || h >= 255) m = fmaxf(m, fabsf(wr[k]));
        }
        red[tid] = m;
        __syncthreads();
        for (int o = 128; o; o >>= 1) {
            if (tid < o) red[tid] = fmaxf(red[tid], red[tid + o]);
            __syncthreads();
        }
        const float mx = red[0];
        const float sW = (mx > 0.f) ? mx * (1.0f / 127.0f) : 1.0f;
        const float invW = 1.0f / sW;
        if (tid == 0) g_Wscale[n] = sW;

        char* wi1 = g_Wi1 + (size_t)n * KI;
        char* wi2 = g_Wi2 + (size_t)n * KI;
        __half* wf1 = g_Wf1 + (size_t)n * KF;
        __half* wf2 = g_Wf2 + (size_t)n * KF;
        for (int k = tid; k < K1; k += 256) {
            const int o = k / 2700;
            const int r = k - o * 2700;
            const int h = r / 10;
            const int wc = r - h * 10;
            const float w = wr[k];
            if (h < 225 || h >= 255) {
                const int pos = (h < 225) ? h : h - 30;
                const int idx = o * 2400 + pos * 10 + wc;
                int q1 = iclamp(__float2int_rn(w * invW), -127, 127);
                float rsd = w - sW * (float)q1;
                int q2 = iclamp(__float2int_rn(rsd * 128.0f * invW), -127, 127);
                wi1[idx] = (char)q1;
                wi2[idx] = (char)q2;
            } else {
                const int idx = o * 300 + (h - 225) * 10 + wc;
                __half w1 = __float2half_rn(w);
                wf1[idx] = w1;
                wf2[idx] = __float2half_rn((w - __half2float(w1)) * 64.0f);
            }
        }
        return;
    }

    // ---- feature role ----
    __shared__ float sd[Fh * Wd];
    __shared__ float sstd[Fh * NWIN];
    __shared__ float sfeat[HPR * NWIN];
    __shared__ float scw[48];
    __shared__ float scb[16];

    const int n = blockIdx.x;
    const float* dptr = data + (size_t)n * (Fh * Wd);
    for (int i = tid; i < Fh * Wd; i += 256) sd[i] = dptr[i];
    if (tid < 48) scw[tid] = conv_w[tid];
    if (tid >= 64 && tid < 80) scb[tid - 64] = conv_b[tid - 64];
    const float bscale = rsqrtf(bn_var[0] + 1e-5f) * bn_gamma[0];
    const float bshift = bn_beta[0] - bn_mean[0] * bscale;
    const float sA = compute_sA(bn_gamma, bn_beta, bn_mean, bn_var, conv_w, conv_b);
    const float invSA = 1.0f / sA;
    __syncthreads();

    if (tid < Fh * NWIN) {
        const int f = tid / NWIN, w = tid % NWIN;
        float* seg = &sd[f * Wd + w * Sw];
        float mean = 0.f;
        #pragma unroll
        for (int s = 0; s < Sw; s++) mean += seg[s];
        mean *= 0.1f;
        float ret = ffill(seg[Sw - 1] / seg[0] - 1.0f);
        float dl = 0.f;
        #pragma unroll
        for (int s = 0; s < Sw; s++) dl += seg[s] * (float)(s + 1);
        dl *= (1.0f / 55.0f);
        float ss = 0.f;
        #pragma unroll
        for (int s = 0; s < Sw; s++) { float sp = seg[s] - mean; seg[s] = sp; ss += sp * sp; }
        const float sdv = sqrtf(ss * (1.0f / 9.0f));
        sstd[tid] = sdv;
        sfeat[(210 + f) * NWIN + w] = ffill(sdv) * bscale + bshift;
        sfeat[(225 + f) * NWIN + w] = ffill(mean / sdv) * bscale + bshift;
        sfeat[(240 + f) * NWIN + w] = ret * bscale + bshift;
        sfeat[(255 + f) * NWIN + w] = ffill(dl) * bscale + bshift;
    }
    __syncthreads();

    for (int idx = tid; idx < Pn * NWIN; idx += 256) {
        const int p = idx / NWIN, w = idx % NWIN;
        int i = 0, rem = p;
        while (rem >= 14 - i) { rem -= 14 - i; i++; }
        const int j = i + 1 + rem;
        const float* si = &sd[i * Wd + w * Sw];
        const float* sj = &sd[j * Wd + w * Sw];
        float dot = 0.f;
        #pragma unroll
        for (int s = 0; s < Sw; s++) dot += si[s] * sj[s];
        const float cov = dot * (1.0f / 9.0f);
        const float corr = ffill(cov / (sstd[i * NWIN + w] * sstd[j * NWIN + w]) * 0.9f);
        sfeat[p * NWIN + w]         = corr * bscale + bshift;
        sfeat[(105 + p) * NWIN + w] = ffill(cov) * bscale + bshift;
    }
    __syncthreads();

    // Conv + ReLU; bounded rows -> int8 2-plane (global scale), unbounded -> fp16 split
    char* pi1 = g_Ai1 + (size_t)n * KI;
    char* pi2 = g_Ai2 + (size_t)n * KI;
    __half* pf1 = g_Af1 + (size_t)n * KF;
    __half* pf2 = g_Af2 + (size_t)n * KF;
    for (int p = tid; p < 1350; p += 256) {
        const int h = p / 5;
        const int wc = (p - h * 5) * 2;
        const float* fr = &sfeat[h * NWIN + wc];
        const float f0 = fr[0], f1 = fr[1], f2 = fr[2], f3 = fr[3];
        const bool bounded = (h < 225 || h >= 255);
        if (bounded) {
            const int pos = (h < 225) ? h : h - 30;
            const int base = pos * 10 + wc;
            #pragma unroll 4
            for (int o = 0; o < 16; o++) {
                const float c0 = scw[3 * o], c1 = scw[3 * o + 1], c2 = scw[3 * o + 2];
                float v0 = fmaxf(scb[o] + c0 * f0 + c1 * f1 + c2 * f2, 0.f);
                float v1 = fmaxf(scb[o] + c0 * f1 + c1 * f2 + c2 * f3, 0.f);
                int q1a = iclamp(__float2int_rn(v0 * invSA), 0, 127);
                int q1b = iclamp(__float2int_rn(v1 * invSA), 0, 127);
                int q2a = iclamp(__float2int_rn((v0 - sA * (float)q1a) * 128.0f * invSA), -127, 127);
                int q2b = iclamp(__float2int_rn((v1 - sA * (float)q1b) * 128.0f * invSA), -127, 127);
                const int idx = o * 2400 + base;
                char2 ca; ca.x = (char)q1a; ca.y = (char)q1b;
                char2 cb2; cb2.x = (char)q2a; cb2.y = (char)q2b;
                *(char2*)(pi1 + idx) = ca;
                *(char2*)(pi2 + idx) = cb2;
            }
        } else {
            const int base = (h - 225) * 10 + wc;
            #pragma unroll 4
            for (int o = 0; o < 16; o++) {
                const float c0 = scw[3 * o], c1 = scw[3 * o + 1], c2 = scw[3 * o + 2];
                float v0 = fmaxf(scb[o] + c0 * f0 + c1 * f1 + c2 * f2, 0.f);
                float v1 = fmaxf(scb[o] + c0 * f1 + c1 * f2 + c2 * f3, 0.f);
                const __half a10 = __float2half_rn(v0 * 0.015625f);
                const __half a11 = __float2half_rn(v1 * 0.015625f);
                const __half a20 = __float2half_rn(v0 - 64.0f * __half2float(a10));
                const __half a21 = __float2half_rn(v1 - 64.0f * __half2float(a11));
                const int idx = o * 300 + base;
                *(__half2*)(pf1 + idx) = __halves2half2(a10, a11);
                *(__half2*)(pf2 + idx) = __halves2half2(a20, a21);
            }
        }
    }
}

// ============================================================================
// Kernel 2: fc1 hybrid GEMM. Phase 1: int8 k32 (KI=38400, BK=128B, 300 stages,
// int32 accs, no mid-loop rescale). Phase 2: fp16 split (KF=4800, 75 stages).
// CTA 128x128, 512 threads, warp tile 32x32. Same smem geometry both phases.
// ============================================================================
__global__ __launch_bounds__(512) void fc1_mma(
    const float* __restrict__ bias,
    const float* __restrict__ bn_gamma, const float* __restrict__ bn_beta,
    const float* __restrict__ bn_mean, const float* __restrict__ bn_var,
    const float* __restrict__ conv_w, const float* __restrict__ conv_b)
{
    extern __shared__ __align__(1024) char smem[];
    const int tid = threadIdx.x;
    const int bx = blockIdx.x;   // N tile 0..3
    const int by = blockIdx.y;   // M tile 0..31
    const int warp = tid >> 5, lane = tid & 31;
    const int wm = warp >> 2;    // 0..3
    const int wn = warp & 3;     // 0..3
    const uint32_t sbase = smem_u32(smem);

    const char* gi0 = g_Ai1 + (size_t)(by * 128) * KI;
    const char* gi1 = g_Ai2 + (size_t)(by * 128) * KI;
    const char* gi2 = g_Wi1 + (size_t)(bx * 128) * KI;
    const char* gi3 = g_Wi2 + (size_t)(bx * 128) * KI;
    const __half* gf0 = g_Af1 + (size_t)(by * 128) * KF;
    const __half* gf1 = g_Af2 + (size_t)(by * 128) * KF;
    const __half* gf2 = g_Wf1 + (size_t)(bx * 128) * KF;
    const __half* gf3 = g_Wf2 + (size_t)(bx * 128) * KF;

    auto issue1 = [&](int kt, int slot) {
        const int k0 = kt * 128;
        const uint32_t sb = sbase + (uint32_t)slot * 65536u;
        #pragma unroll
        for (int p = 0; p < 8; p++) {
            const int plane = p >> 1;
            const int v = tid + ((p & 1) << 9);
            const int row = v >> 3;
            const int c = v & 7;
            const char* g =
                (plane == 0 ? gi0 : plane == 1 ? gi1 : plane == 2 ? gi2 : gi3)
                + (size_t)row * KI + k0 + c * 16;
            const uint32_t sa = sb + (uint32_t)plane * 16384u
                              + SWZ((uint32_t)(row * 128 + c * 16));
            asm volatile("cp.async.cg.shared.global [%0], [%1], 16;"
                         :: "r"(sa), "l"(g));
        }
        asm volatile("cp.async.commit_group;");
    };
    auto issue2 = [&](int kt, int slot) {
        const int k0 = kt * 64;
        const uint32_t sb = sbase + (uint32_t)slot * 65536u;
        #pragma unroll
        for (int p = 0; p < 8; p++) {
            const int plane = p >> 1;
            const int v = tid + ((p & 1) << 9);
            const int row = v >> 3;
            const int c = v & 7;
            const __half* g =
                (plane == 0 ? gf0 : plane == 1 ? gf1 : plane == 2 ? gf2 : gf3)
                + (size_t)row * KF + k0 + c * 8;
            const uint32_t sa = sb + (uint32_t)plane * 16384u
                              + SWZ((uint32_t)(row * 128 + c * 16));
            asm volatile("cp.async.cg.shared.global [%0], [%1], 16;"
                         :: "r"(sa), "l"(g));
        }
        asm volatile("cp.async.commit_group;");
    };

    issue1(0, 0);
    issue1(1, 1);

    const uint32_t a_row_off = (uint32_t)((wm * 32 + (lane & 15)) * 128);
    const uint32_t a_k_off   = (uint32_t)((lane >> 4) << 4);
    const uint32_t b_row_off = (uint32_t)((wn * 32 + ((lane >> 4) << 3) + (lane & 7)) * 128);
    const uint32_t b_k_off   = (uint32_t)(((lane >> 3) & 1) << 4);

    // ---------------- Phase 1: int8 ----------------
    int imain[2][4][4], icross[2][4][4];
    #pragma unroll
    for (int i = 0; i < 2; i++)
        #pragma unroll
        for (int j = 0; j < 4; j++)
            #pragma unroll
            for (int q = 0; q < 4; q++) { imain[i][j][q] = 0; icross[i][j][q] = 0; }

    for (int kt = 0; kt < NTI; kt++) {
        asm volatile("cp.async.wait_group 1;");
        __syncthreads();
        const int nx = kt + 2;
        if (nx < NTI) issue1(nx, nx % 3);
        else issue2(nx - NTI, nx % 3);

        const uint32_t sb = sbase + (uint32_t)(kt % 3) * 65536u;
        #pragma unroll
        for (int s = 0; s < 4; s++) {
            uint32_t a1f[2][4], a2f[2][4];
            #pragma unroll
            for (int mt = 0; mt < 2; mt++) {
                const uint32_t off = a_row_off + mt * 2048 + s * 32 + a_k_off;
                ldsm4(a1f[mt], sb + SWZ(off));
                ldsm4(a2f[mt], sb + 16384u + SWZ(off));
            }
            uint32_t w1f[2][4], w2f[2][4];
            #pragma unroll
            for (int q = 0; q < 2; q++) {
                const uint32_t off = b_row_off + q * 2048 + s * 32 + b_k_off;
                ldsm4(w1f[q], sb + 32768u + SWZ(off));
                ldsm4(w2f[q], sb + 49152u + SWZ(off));
            }
            #pragma unroll
            for (int mt = 0; mt < 2; mt++)
                #pragma unroll
                for (int nt = 0; nt < 4; nt++)
                    mma_s8(imain[mt][nt], a1f[mt], &w1f[nt >> 1][(nt & 1) << 1]);
            #pragma unroll
            for (int mt = 0; mt < 2; mt++)
                #pragma unroll
                for (int nt = 0; nt < 4; nt++)
                    mma_s8(icross[mt][nt], a1f[mt], &w2f[nt >> 1][(nt & 1) << 1]);
            #pragma unroll
            for (int mt = 0; mt < 2; mt++)
                #pragma unroll
                for (int nt = 0; nt < 4; nt++)
                    mma_s8(icross[mt][nt], a2f[mt], &w1f[nt >> 1][(nt & 1) << 1]);
        }
    }

    // fold int accumulators -> float (registers only; pipeline keeps flowing)
    const float sAv = compute_sA(bn_gamma, bn_beta, bn_mean, bn_var, conv_w, conv_b);
    float fin[2][4][4];
    #pragma unroll
    for (int nt = 0; nt < 4; nt++) {
        const int c = bx * 128 + wn * 32 + nt * 8 + ((lane & 3) << 1);
        const float s0 = sAv * __ldg(g_Wscale + c);
        const float s1 = sAv * __ldg(g_Wscale + c + 1);
        #pragma unroll
        for (int mt = 0; mt < 2; mt++) {
            fin[mt][nt][0] = s0 * ((float)imain[mt][nt][0] + (float)icross[mt][nt][0] * 0.0078125f);
            fin[mt][nt][1] = s1 * ((float)imain[mt][nt][1] + (float)icross[mt][nt][1] * 0.0078125f);
            fin[mt][nt][2] = s0 * ((float)imain[mt][nt][2] + (float)icross[mt][nt][2] * 0.0078125f);
            fin[mt][nt][3] = s1 * ((float)imain[mt][nt][3] + (float)icross[mt][nt][3] * 0.0078125f);
        }
    }

    // ---------------- Phase 2: fp16 ----------------
    float macc[2][4][4];
    uint32_t hacc[2][4][2];
    #pragma unroll
    for (int i = 0; i < 2; i++)
        #pragma unroll
        for (int j = 0; j < 4; j++) {
            #pragma unroll
            for (int q = 0; q < 4; q++) macc[i][j][q] = 0.f;
            hacc[i][j][0] = 0u; hacc[i][j][1] = 0u;
        }

    for (int kt = 0; kt < NTF; kt++) {
        asm volatile("cp.async.wait_group 1;");
        __syncthreads();
        const int nx = kt + 2;
        if (nx < NTF) issue2(nx, (NTI + nx) % 3);
        else asm volatile("cp.async.commit_group;");

        const uint32_t sb = sbase + (uint32_t)((NTI + kt) % 3) * 65536u;
        #pragma unroll
        for (int s = 0; s < 4; s++) {
            uint32_t a1f[2][4], a2f[2][4];
            #pragma unroll
            for (int mt = 0; mt < 2; mt++) {
                const uint32_t off = a_row_off + mt * 2048 + s * 32 + a_k_off;
                ldsm4(a1f[mt], sb + SWZ(off));
                ldsm4(a2f[mt], sb + 16384u + SWZ(off));
            }
            uint32_t w1f[2][4], w2f[2][4];
            #pragma unroll
            for (int q = 0; q < 2; q++) {
                const uint32_t off = b_row_off + q * 2048 + s * 32 + b_k_off;
                ldsm4(w1f[q], sb + 32768u + SWZ(off));
                ldsm4(w2f[q], sb + 49152u + SWZ(off));
            }
            #pragma unroll
            for (int mt = 0; mt < 2; mt++)
                #pragma unroll
                for (int nt = 0; nt < 4; nt++)
                    hmma_f32(macc[mt][nt], a1f[mt], &w1f[nt >> 1][(nt & 1) << 1]);
            #pragma unroll
            for (int mt = 0; mt < 2; mt++)
                #pragma unroll
                for (int nt = 0; nt < 4; nt++)
                    hmma_f16(hacc[mt][nt], a1f[mt], &w2f[nt >> 1][(nt & 1) << 1]);
            #pragma unroll
            for (int mt = 0; mt < 2; mt++)
                #pragma unroll
                for (int nt = 0; nt < 4; nt++)
                    hmma_f16(hacc[mt][nt], a2f[mt], &w1f[nt >> 1][(nt & 1) << 1]);
        }
    }

    // epilogue
    #pragma unroll
    for (int mt = 0; mt < 2; mt++) {
        const int r0 = by * 128 + wm * 32 + mt * 16 + (lane >> 2);
        #pragma unroll
        for (int nt = 0; nt < 4; nt++) {
            const int c = bx * 128 + wn * 32 + nt * 8 + ((lane & 3) << 1);
            const float b0 = __ldg(bias + c), b1 = __ldg(bias + c + 1);
            float2 c0 = __half22float2(*(half2*)&hacc[mt][nt][0]);
            float2 c1 = __half22float2(*(half2*)&hacc[mt][nt][1]);
            float2 v0, v1;
            v0.x = fmaxf(fin[mt][nt][0] + 64.0f * macc[mt][nt][0] + c0.x + b0, 0.f);
            v0.y = fmaxf(fin[mt][nt][1] + 64.0f * macc[mt][nt][1] + c0.y + b1, 0.f);
            v1.x = fmaxf(fin[mt][nt][2] + 64.0f * macc[mt][nt][2] + c1.x + b0, 0.f);
            v1.y = fmaxf(fin[mt][nt][3] + 64.0f * macc[mt][nt][3] + c1.y + b1, 0.f);
            *(float2*)(g_y1 + (size_t)r0 * N1 + c) = v0;
            *(float2*)(g_y1 + (size_t)(r0 + 8) * N1 + c) = v1;
        }
    }
}

// ============================================================================
// Kernel 3: fused fc2(sigmoid) + fc3 -- 256 blocks of 16 rows
// ============================================================================
__global__ __launch_bounds__(256) void fc23_kernel(
    const float* __restrict__ w2, const float* __restrict__ b2,
    const float* __restrict__ w3, const float* __restrict__ b3,
    float* __restrict__ out)
{
    __shared__ float As[32][16];
    __shared__ float Bs[32][128];
    __shared__ float sbuf[16][128];
    __shared__ float sw3[128];

    const int tid = threadIdx.x;
    const int mb = blockIdx.x;
    const float* Ab = g_y1 + (size_t)(mb * 16) * N1;
    if (tid < 128) sw3[tid] = w3[tid];
    const int tm = tid >> 5;
    const int tn = tid & 31;

    float acc[2][4] = {};
    for (int kt = 0; kt < 16; kt++) {
        const int k0 = kt * 32;
        if (tid < 128) {
            const int row = tid >> 3, kq = (tid & 7) << 2;
            float4 a = *(const float4*)(Ab + (size_t)row * N1 + k0 + kq);
            As[kq + 0][row] = a.x; As[kq + 1][row] = a.y;
            As[kq + 2][row] = a.z; As[kq + 3][row] = a.w;
        }
        #pragma unroll
        for (int q = 0; q < 4; q++) {
            const int v = tid + q * 256;
            const int row = v >> 3, kq = (v & 7) << 2;
            float4 b = *(const float4*)(w2 + (size_t)row * N1 + k0 + kq);
            Bs[kq + 0][row] = b.x; Bs[kq + 1][row] = b.y;
            Bs[kq + 2][row] = b.z; Bs[kq + 3][row] = b.w;
        }
        __syncthreads();
        #pragma unroll
        for (int k = 0; k < 32; k++) {
            float ra[2], rb[4];
            ra[0] = As[k][tm * 2];
            ra[1] = As[k][tm * 2 + 1];
            *(float4*)rb = *(const float4*)&Bs[k][tn * 4];
            #pragma unroll
            for (int i = 0; i < 2; i++)
                #pragma unroll
                for (int j = 0; j < 4; j++) acc[i][j] += ra[i] * rb[j];
        }
        __syncthreads();
    }

    #pragma unroll
    for (int i = 0; i < 2; i++)
        #pragma unroll
        for (int j = 0; j < 4; j++) {
            const float v = acc[i][j] + b2[tn * 4 + j];
            sbuf[tm * 2 + i][tn * 4 + j] = 1.0f / (1.0f + expf(-v));
        }
    __syncthreads();

    #pragma unroll
    for (int r = 0; r < 2; r++) {
        const int row = tm * 2 + r;
        float s = sbuf[row][tn] * sw3[tn] + sbuf[row][tn + 32] * sw3[tn + 32]
                + sbuf[row][tn + 64] * sw3[tn + 64] + sbuf[row][tn + 96] * sw3[tn + 96];
        #pragma unroll
        for (int o = 16; o; o >>= 1) s += __shfl_down_sync(0xffffffffu, s, o);
        if (tn == 0) out[mb * 16 + row] = s + b3[0];
    }
}

// ============================================================================
extern "C" void kernel_launch(void* const* d_in, const int* in_sizes, int n_in,
                              void* d_out, int out_size) {
    const float* data   = (const float*)d_in[0];
    const float* gamma  = (const float*)d_in[1];
    const float* beta   = (const float*)d_in[2];
    const float* mean   = (const float*)d_in[3];
    const float* var    = (const float*)d_in[4];
    const float* conv_w = (const float*)d_in[5];
    const float* conv_b = (const float*)d_in[6];
    const float* fc1_w  = (const float*)d_in[7];
    const float* fc1_b  = (const float*)d_in[8];
    const float* fc2_w  = (const float*)d_in[9];
    const float* fc2_b  = (const float*)d_in[10];
    const float* fc3_w  = (const float*)d_in[11];
    const float* fc3_b  = (const float*)d_in[12];
    float* out = (float*)d_out;

    const int smem_sz = STAGES * 4 * 16384;  // 196608
    cudaFuncSetAttribute(fc1_mma, cudaFuncAttributeMaxDynamicSharedMemorySize, smem_sz);

    feat_kernel<<<N_SAMP + N1, 256>>>(data, gamma, beta, mean, var,
                                      conv_w, conv_b, fc1_w);
    dim3 g1(4, 32);
    fc1_mma<<<g1, 512, smem_sz>>>(fc1_b, gamma, beta, mean, var, conv_w, conv_b);
    fc23_kernel<<<256, 256>>>(fc2_w, fc2_b, fc3_w, fc3_b, out);
}

// round 9
// speedup vs baseline: 2.5497x; 2.5497x over previous
#include <cuda_runtime.h>
#include <cuda_fp16.h>
#include <cstdint>

#define N_SAMP 4096
#define Fh 15
#define Wd 120
#define NWIN 12
#define Sw 10
#define Pn 105
#define HPR 270
#define K1 43200
#define N1 512
#define BK 64
#define NT (K1 / BK)   // 675
#define STAGES 3
#define WB2 2048       // weight-split blocks (grid-stride)

// ---------------- device-global scratch (no allocations anywhere) ----------
// A = 64*a1 + a2 (fp16 planes); W = w1 + w2/64 (w2 stored pre-scaled by 64)
__device__ __half g_A1[(size_t)N_SAMP * K1];  // 354 MB
__device__ __half g_A2[(size_t)N_SAMP * K1];  // 354 MB
__device__ __half g_W1[(size_t)N1 * K1];      // 44 MB
__device__ __half g_W2[(size_t)N1 * K1];      // 44 MB
__device__ float g_y1[(size_t)N_SAMP * N1];   // 8 MB

// ---------------- helpers ---------------------------------------------------
__device__ __forceinline__ float ffill(float x) {
    unsigned u = __float_as_uint(x);
    return ((u & 0x7f800000u) == 0x7f800000u) ? 0.0f : x;
}
__device__ __forceinline__ uint32_t smem_u32(const void* p) {
    uint32_t a;
    asm("{ .reg .u64 t; cvta.to.shared.u64 t, %1; cvt.u32.u64 %0, t; }" : "=r"(a) : "l"(p));
    return a;
}
#define SWZ(o) ((o) ^ (((o) >> 3) & 0x70))

__device__ __forceinline__ void ldsm4(uint32_t* r, uint32_t addr) {
    asm volatile("ldmatrix.sync.aligned.m8n8.x4.shared.b16 {%0,%1,%2,%3}, [%4];"
                 : "=r"(r[0]), "=r"(r[1]), "=r"(r[2]), "=r"(r[3]) : "r"(addr));
}
__device__ __forceinline__ void hmma_f32(float* d, const uint32_t* a, const uint32_t* b) {
    asm volatile(
        "mma.sync.aligned.m16n8k16.row.col.f32.f16.f16.f32 "
        "{%0,%1,%2,%3},{%4,%5,%6,%7},{%8,%9},{%0,%1,%2,%3};"
        : "+f"(d[0]), "+f"(d[1]), "+f"(d[2]), "+f"(d[3])
        : "r"(a[0]), "r"(a[1]), "r"(a[2]), "r"(a[3]), "r"(b[0]), "r"(b[1]));
}
__device__ __forceinline__ void hmma_f16(uint32_t* d, const uint32_t* a, const uint32_t* b) {
    asm volatile(
        "mma.sync.aligned.m16n8k16.row.col.f16.f16.f16.f16 "
        "{%0,%1},{%2,%3,%4,%5},{%6,%7},{%0,%1};"
        : "+r"(d[0]), "+r"(d[1])
        : "r"(a[0]), "r"(a[1]), "r"(a[2]), "r"(a[3]), "r"(b[0]), "r"(b[1]));
}

// ============================================================================
// Kernel 1 (fused): blocks [0,4096) = features+BN+conv+ReLU -> A planes
//                   blocks [4096, 4096+WB2) = fc1 weight split (grid-stride)
// ============================================================================
__global__ __launch_bounds__(256) void feat_kernel(
    const float* __restrict__ data,
    const float* __restrict__ bn_gamma, const float* __restrict__ bn_beta,
    const float* __restrict__ bn_mean, const float* __restrict__ bn_var,
    const float* __restrict__ conv_w, const float* __restrict__ conv_b,
    const float* __restrict__ fc1_w)
{
    const int tid = threadIdx.x;

    if (blockIdx.x >= N_SAMP) {
        // ---- weight-split role: grid-stride ----
        const size_t stride = (size_t)WB2 * 256;
        const size_t total = (size_t)N1 * K1 / 4;
        for (size_t t = (size_t)(blockIdx.x - N_SAMP) * 256 + tid; t < total; t += stride) {
            const size_t i = t * 4;
            float4 v = *(const float4*)(fc1_w + i);
            __half w1x = __float2half_rn(v.x);
            __half w1y = __float2half_rn(v.y);
            __half w1z = __float2half_rn(v.z);
            __half w1w = __float2half_rn(v.w);
            ushort4 h1, h2;
            h1.x = __half_as_ushort(w1x);
            h1.y = __half_as_ushort(w1y);
            h1.z = __half_as_ushort(w1z);
            h1.w = __half_as_ushort(w1w);
            h2.x = __half_as_ushort(__float2half_rn((v.x - __half2float(w1x)) * 64.0f));
            h2.y = __half_as_ushort(__float2half_rn((v.y - __half2float(w1y)) * 64.0f));
            h2.z = __half_as_ushort(__float2half_rn((v.z - __half2float(w1z)) * 64.0f));
            h2.w = __half_as_ushort(__float2half_rn((v.w - __half2float(w1w)) * 64.0f));
            *(ushort4*)((unsigned short*)g_W1 + i) = h1;
            *(ushort4*)((unsigned short*)g_W2 + i) = h2;
        }
        return;
    }

    // ---- feature role ----
    __shared__ float sd[Fh * Wd];
    __shared__ float sstd[Fh * NWIN];
    __shared__ float sfeat[HPR * NWIN];
    __shared__ float scw[48];
    __shared__ float scb[16];

    const int n = blockIdx.x;
    const float* dptr = data + (size_t)n * (Fh * Wd);
    for (int i = tid; i < Fh * Wd; i += 256) sd[i] = dptr[i];
    if (tid < 48) scw[tid] = conv_w[tid];
    if (tid >= 64 && tid < 80) scb[tid - 64] = conv_b[tid - 64];
    const float bscale = rsqrtf(bn_var[0] + 1e-5f) * bn_gamma[0];
    const float bshift = bn_beta[0] - bn_mean[0] * bscale;
    __syncthreads();

    if (tid < Fh * NWIN) {
        const int f = tid / NWIN, w = tid % NWIN;
        float* seg = &sd[f * Wd + w * Sw];
        float mean = 0.f;
        #pragma unroll
        for (int s = 0; s < Sw; s++) mean += seg[s];
        mean *= 0.1f;
        float ret = ffill(seg[Sw - 1] / seg[0] - 1.0f);
        float dl = 0.f;
        #pragma unroll
        for (int s = 0; s < Sw; s++) dl += seg[s] * (float)(s + 1);
        dl *= (1.0f / 55.0f);
        float ss = 0.f;
        #pragma unroll
        for (int s = 0; s < Sw; s++) { float sp = seg[s] - mean; seg[s] = sp; ss += sp * sp; }
        const float sdv = sqrtf(ss * (1.0f / 9.0f));
        sstd[tid] = sdv;
        sfeat[(210 + f) * NWIN + w] = ffill(sdv) * bscale + bshift;
        sfeat[(225 + f) * NWIN + w] = ffill(mean / sdv) * bscale + bshift;
        sfeat[(240 + f) * NWIN + w] = ret * bscale + bshift;
        sfeat[(255 + f) * NWIN + w] = ffill(dl) * bscale + bshift;
    }
    __syncthreads();

    for (int idx = tid; idx < Pn * NWIN; idx += 256) {
        const int p = idx / NWIN, w = idx % NWIN;
        int i = 0, rem = p;
        while (rem >= 14 - i) { rem -= 14 - i; i++; }
        const int j = i + 1 + rem;
        const float* si = &sd[i * Wd + w * Sw];
        const float* sj = &sd[j * Wd + w * Sw];
        float dot = 0.f;
        #pragma unroll
        for (int s = 0; s < Sw; s++) dot += si[s] * sj[s];
        const float cov = dot * (1.0f / 9.0f);
        const float corr = ffill(cov / (sstd[i * NWIN + w] * sstd[j * NWIN + w]) * 0.9f);
        sfeat[p * NWIN + w]         = corr * bscale + bshift;
        sfeat[(105 + p) * NWIN + w] = ffill(cov) * bscale + bshift;
    }
    __syncthreads();

    // Conv + ReLU + fp16 split; streaming stores (written once, reread from DRAM)
    __half* p1 = g_A1 + (size_t)n * K1;
    __half* p2 = g_A2 + (size_t)n * K1;
    for (int p = tid; p < 1350; p += 256) {
        const int h = p / 5;
        const int wc = (p - h * 5) * 2;
        const float* fr = &sfeat[h * NWIN + wc];
        const float f0 = fr[0], f1 = fr[1], f2 = fr[2], f3 = fr[3];
        const int base = h * 10 + wc;
        #pragma unroll 4
        for (int o = 0; o < 16; o++) {
            const float c0 = scw[3 * o], c1 = scw[3 * o + 1], c2 = scw[3 * o + 2];
            float v0 = fmaxf(scb[o] + c0 * f0 + c1 * f1 + c2 * f2, 0.f);
            float v1 = fmaxf(scb[o] + c0 * f1 + c1 * f2 + c2 * f3, 0.f);
            const __half a10 = __float2half_rn(v0 * 0.015625f);
            const __half a11 = __float2half_rn(v1 * 0.015625f);
            const __half a20 = __float2half_rn(v0 - 64.0f * __half2float(a10));
            const __half a21 = __float2half_rn(v1 - 64.0f * __half2float(a11));
            const int idx = o * 2700 + base;
            __stcs((__half2*)(p1 + idx), __halves2half2(a10, a11));
            __stcs((__half2*)(p2 + idx), __halves2half2(a20, a21));
        }
    }
}

// ============================================================================
// Kernel 2: fc1 split-fp16 GEMM, 148-CTA single-wave tiling.
// Grid 148 = 37 M-chunks x 4 N-tiles. M-chunks: 34x112 rows + 3x96 rows.
// Warp grid 4x4 (warp tile 32x32); warps with wm=3 run 1 (or 0) m-frags --
// one light warp per SMSP -> balanced 7/8 load vs 128-row tile.
// y1 = relu( 64*(A1@W1^T)[f32acc] + (A1@W2^T + A2@W1^T)[f16acc] + b )
// ============================================================================
__global__ __launch_bounds__(512) void fc1_mma(const float* __restrict__ bias)
{
    extern __shared__ __align__(1024) char smem[];
    const int tid = threadIdx.x;
    const int bx = blockIdx.x & 3;        // N tile 0..3
    const int c  = blockIdx.x >> 2;       // M chunk 0..36
    const int by_off = (c < 34) ? c * 112 : 3808 + (c - 34) * 96;
    const int rows   = (c < 34) ? 112 : 96;
    const int warp = tid >> 5, lane = tid & 31;
    const int wm = warp >> 2;    // 0..3
    const int wn = warp & 3;     // 0..3
    const int wrows = rows - wm * 32;
    const int mfc = (wrows >= 32) ? 2 : ((wrows >= 16) ? 1 : 0);
    const uint32_t sbase = smem_u32(smem);

    const __half* gp0 = g_A1 + (size_t)by_off * K1;
    const __half* gp1 = g_A2 + (size_t)by_off * K1;
    const __half* gp2 = g_W1 + (size_t)(bx * 128) * K1;
    const __half* gp3 = g_W2 + (size_t)(bx * 128) * K1;

    auto issue_stage = [&](int kt, int slot) {
        const int k0 = kt * BK;
        const uint32_t sb = sbase + (uint32_t)slot * 65536u;
        #pragma unroll
        for (int p = 0; p < 8; p++) {
            const int plane = p >> 1;
            const int v = tid + ((p & 1) << 9);
            const int row = v >> 3;      // 0..127
            const int cch = v & 7;       // 16B chunk
            // clamp A-plane rows to valid sample range (W planes full 128)
            const int grow = (plane < 2) ? (row < rows ? row : rows - 1) : row;
            const __half* g =
                (plane == 0 ? gp0 : plane == 1 ? gp1 : plane == 2 ? gp2 : gp3)
                + (size_t)grow * K1 + k0 + cch * 8;
            const uint32_t sa = sb + (uint32_t)plane * 16384u
                              + SWZ((uint32_t)(row * 128 + cch * 16));
            asm volatile("cp.async.cg.shared.global [%0], [%1], 16;"
                         :: "r"(sa), "l"(g));
        }
        asm volatile("cp.async.commit_group;");
    };

    issue_stage(0, 0);
    issue_stage(1, 1);

    float acc[2][4][4];
    uint32_t hacc[2][4][2];
    #pragma unroll
    for (int i = 0; i < 2; i++)
        #pragma unroll
        for (int j = 0; j < 4; j++) {
            #pragma unroll
            for (int q = 0; q < 4; q++) acc[i][j][q] = 0.f;
            hacc[i][j][0] = 0u; hacc[i][j][1] = 0u;
        }

    const uint32_t a_row_off = (uint32_t)((wm * 32 + (lane & 15)) * 128);
    const uint32_t a_k_off   = (uint32_t)((lane >> 4) << 4);
    const uint32_t b_row_off = (uint32_t)((wn * 32 + ((lane >> 4) << 3) + (lane & 7)) * 128);
    const uint32_t b_k_off   = (uint32_t)(((lane >> 3) & 1) << 4);

    for (int kt = 0; kt < NT; kt++) {
        asm volatile("cp.async.wait_group 1;");
        __syncthreads();
        if (kt + 2 < NT) issue_stage(kt + 2, (kt + 2) % STAGES);
        else asm volatile("cp.async.commit_group;");

        const uint32_t sb = sbase + (uint32_t)(kt % STAGES) * 65536u;
        #pragma unroll
        for (int s = 0; s < 4; s++) {
            uint32_t a1f[2][4], a2f[2][4];
            #pragma unroll
            for (int mt = 0; mt < 2; mt++) {
                if (mt < mfc) {
                    const uint32_t off = a_row_off + mt * 2048 + s * 32 + a_k_off;
                    ldsm4(a1f[mt], sb + SWZ(off));
                    ldsm4(a2f[mt], sb + 16384u + SWZ(off));
                }
            }
            uint32_t w1f[2][4], w2f[2][4];
            #pragma unroll
            for (int q = 0; q < 2; q++) {
                const uint32_t off = b_row_off + q * 2048 + s * 32 + b_k_off;
                ldsm4(w1f[q], sb + 32768u + SWZ(off));
                ldsm4(w2f[q], sb + 49152u + SWZ(off));
            }
            #pragma unroll
            for (int mt = 0; mt < 2; mt++)
                if (mt < mfc) {
                    #pragma unroll
                    for (int nt = 0; nt < 4; nt++)
                        hmma_f32(acc[mt][nt], a1f[mt], &w1f[nt >> 1][(nt & 1) << 1]);
                }
            #pragma unroll
            for (int mt = 0; mt < 2; mt++)
                if (mt < mfc) {
                    #pragma unroll
                    for (int nt = 0; nt < 4; nt++)
                        hmma_f16(hacc[mt][nt], a1f[mt], &w2f[nt >> 1][(nt & 1) << 1]);
                }
            #pragma unroll
            for (int mt = 0; mt < 2; mt++)
                if (mt < mfc) {
                    #pragma unroll
                    for (int nt = 0; nt < 4; nt++)
                        hmma_f16(hacc[mt][nt], a2f[mt], &w1f[nt >> 1][(nt & 1) << 1]);
                }
        }
    }

    // epilogue: y = 64*hh + cross + bias, relu
    #pragma unroll
    for (int mt = 0; mt < 2; mt++) {
        if (mt >= mfc) break;
        const int r0 = by_off + wm * 32 + mt * 16 + (lane >> 2);
        #pragma unroll
        for (int nt = 0; nt < 4; nt++) {
            const int cc = bx * 128 + wn * 32 + nt * 8 + ((lane & 3) << 1);
            const float b0 = __ldg(bias + cc), b1 = __ldg(bias + cc + 1);
            float2 c0 = __half22float2(*(half2*)&hacc[mt][nt][0]);
            float2 c1 = __half22float2(*(half2*)&hacc[mt][nt][1]);
            float2 v0, v1;
            v0.x = fmaxf(64.0f * acc[mt][nt][0] + c0.x + b0, 0.f);
            v0.y = fmaxf(64.0f * acc[mt][nt][1] + c0.y + b1, 0.f);
            v1.x = fmaxf(64.0f * acc[mt][nt][2] + c1.x + b0, 0.f);
            v1.y = fmaxf(64.0f * acc[mt][nt][3] + c1.y + b1, 0.f);
            *(float2*)(g_y1 + (size_t)r0 * N1 + cc) = v0;
            *(float2*)(g_y1 + (size_t)(r0 + 8) * N1 + cc) = v1;
        }
    }
}

// ============================================================================
// Kernel 3: fused fc2(sigmoid) + fc3 -- 256 blocks of 16 rows
// ============================================================================
__global__ __launch_bounds__(256) void fc23_kernel(
    const float* __restrict__ w2, const float* __restrict__ b2,
    const float* __restrict__ w3, const float* __restrict__ b3,
    float* __restrict__ out)
{
    __shared__ float As[32][16];
    __shared__ float Bs[32][128];
    __shared__ float sbuf[16][128];
    __shared__ float sw3[128];

    const int tid = threadIdx.x;
    const int mb = blockIdx.x;
    const float* Ab = g_y1 + (size_t)(mb * 16) * N1;
    if (tid < 128) sw3[tid] = w3[tid];
    const int tm = tid >> 5;
    const int tn = tid & 31;

    float acc[2][4] = {};
    for (int kt = 0; kt < 16; kt++) {
        const int k0 = kt * 32;
        if (tid < 128) {
            const int row = tid >> 3, kq = (tid & 7) << 2;
            float4 a = *(const float4*)(Ab + (size_t)row * N1 + k0 + kq);
            As[kq + 0][row] = a.x; As[kq + 1][row] = a.y;
            As[kq + 2][row] = a.z; As[kq + 3][row] = a.w;
        }
        #pragma unroll
        for (int q = 0; q < 4; q++) {
            const int v = tid + q * 256;
            const int row = v >> 3, kq = (v & 7) << 2;
            float4 b = *(const float4*)(w2 + (size_t)row * N1 + k0 + kq);
            Bs[kq + 0][row] = b.x; Bs[kq + 1][row] = b.y;
            Bs[kq + 2][row] = b.z; Bs[kq + 3][row] = b.w;
        }
        __syncthreads();
        #pragma unroll
        for (int k = 0; k < 32; k++) {
            float ra[2], rb[4];
            ra[0] = As[k][tm * 2];
            ra[1] = As[k][tm * 2 + 1];
            *(float4*)rb = *(const float4*)&Bs[k][tn * 4];
            #pragma unroll
            for (int i = 0; i < 2; i++)
                #pragma unroll
                for (int j = 0; j < 4; j++) acc[i][j] += ra[i] * rb[j];
        }
        __syncthreads();
    }

    #pragma unroll
    for (int i = 0; i < 2; i++)
        #pragma unroll
        for (int j = 0; j < 4; j++) {
            const float v = acc[i][j] + b2[tn * 4 + j];
            sbuf[tm * 2 + i][tn * 4 + j] = 1.0f / (1.0f + expf(-v));
        }
    __syncthreads();

    #pragma unroll
    for (int r = 0; r < 2; r++) {
        const int row = tm * 2 + r;
        float s = sbuf[row][tn] * sw3[tn] + sbuf[row][tn + 32] * sw3[tn + 32]
                + sbuf[row][tn + 64] * sw3[tn + 64] + sbuf[row][tn + 96] * sw3[tn + 96];
        #pragma unroll
        for (int o = 16; o; o >>= 1) s += __shfl_down_sync(0xffffffffu, s, o);
        if (tn == 0) out[mb * 16 + row] = s + b3[0];
    }
}

// ============================================================================
extern "C" void kernel_launch(void* const* d_in, const int* in_sizes, int n_in,
                              void* d_out, int out_size) {
    const float* data   = (const float*)d_in[0];
    const float* gamma  = (const float*)d_in[1];
    const float* beta   = (const float*)d_in[2];
    const float* mean   = (const float*)d_in[3];
    const float* var    = (const float*)d_in[4];
    const float* conv_w = (const float*)d_in[5];
    const float* conv_b = (const float*)d_in[6];
    const float* fc1_w  = (const float*)d_in[7];
    const float* fc1_b  = (const float*)d_in[8];
    const float* fc2_w  = (const float*)d_in[9];
    const float* fc2_b  = (const float*)d_in[10];
    const float* fc3_w  = (const float*)d_in[11];
    const float* fc3_b  = (const float*)d_in[12];
    float* out = (float*)d_out;

    const int smem_sz = STAGES * 4 * 16384;  // 196608
    cudaFuncSetAttribute(fc1_mma, cudaFuncAttributeMaxDynamicSharedMemorySize, smem_sz);

    feat_kernel<<<N_SAMP + WB2, 256>>>(data, gamma, beta, mean, var,
                                       conv_w, conv_b, fc1_w);
    fc1_mma<<<148, 512, smem_sz>>>(fc1_b);
    fc23_kernel<<<256, 256>>>(fc2_w, fc2_b, fc3_w, fc3_b, out);
}

// round 10
// speedup vs baseline: 2.8082x; 1.1014x over previous
#include <cuda_runtime.h>
#include <cuda_fp16.h>
#include <cstdint>

#define N_SAMP 4096
#define Fh 15
#define Wd 120
#define NWIN 12
#define Sw 10
#define Pn 105
#define HPR 270
#define K1 43200
#define N1 512
#define BK 64
#define NT (K1 / BK)   // 675
#define KSPLIT 9
#define PSTG (NT / KSPLIT)  // 75 stages per piece
#define STAGES 3
#define WB2 2048       // weight-split blocks (grid-stride)

// ---------------- device-global scratch (no allocations anywhere) ----------
// A = 64*a1 + a2 (fp16 planes); W = w1 + w2/64 (w2 stored pre-scaled by 64)
__device__ __half g_A1[(size_t)N_SAMP * K1];  // 354 MB
__device__ __half g_A2[(size_t)N_SAMP * K1];  // 354 MB
__device__ __half g_W1[(size_t)N1 * K1];      // 44 MB
__device__ __half g_W2[(size_t)N1 * K1];      // 44 MB
__device__ float g_y1s[(size_t)KSPLIT * N_SAMP * N1];  // 75.5 MB partial sums

// ---------------- helpers ---------------------------------------------------
__device__ __forceinline__ float ffill(float x) {
    unsigned u = __float_as_uint(x);
    return ((u & 0x7f800000u) == 0x7f800000u) ? 0.0f : x;
}
__device__ __forceinline__ uint32_t smem_u32(const void* p) {
    uint32_t a;
    asm("{ .reg .u64 t; cvta.to.shared.u64 t, %1; cvt.u32.u64 %0, t; }" : "=r"(a) : "l"(p));
    return a;
}
#define SWZ(o) ((o) ^ (((o) >> 3) & 0x70))

__device__ __forceinline__ void ldsm4(uint32_t* r, uint32_t addr) {
    asm volatile("ldmatrix.sync.aligned.m8n8.x4.shared.b16 {%0,%1,%2,%3}, [%4];"
                 : "=r"(r[0]), "=r"(r[1]), "=r"(r[2]), "=r"(r[3]) : "r"(addr));
}
__device__ __forceinline__ void hmma_f32(float* d, const uint32_t* a, const uint32_t* b) {
    asm volatile(
        "mma.sync.aligned.m16n8k16.row.col.f32.f16.f16.f32 "
        "{%0,%1,%2,%3},{%4,%5,%6,%7},{%8,%9},{%0,%1,%2,%3};"
        : "+f"(d[0]), "+f"(d[1]), "+f"(d[2]), "+f"(d[3])
        : "r"(a[0]), "r"(a[1]), "r"(a[2]), "r"(a[3]), "r"(b[0]), "r"(b[1]));
}
__device__ __forceinline__ void hmma_f16(uint32_t* d, const uint32_t* a, const uint32_t* b) {
    asm volatile(
        "mma.sync.aligned.m16n8k16.row.col.f16.f16.f16.f16 "
        "{%0,%1},{%2,%3,%4,%5},{%6,%7},{%0,%1};"
        : "+r"(d[0]), "+r"(d[1])
        : "r"(a[0]), "r"(a[1]), "r"(a[2]), "r"(a[3]), "r"(b[0]), "r"(b[1]));
}

// ============================================================================
// Kernel 1 (fused): blocks [0,4096) = features+BN+conv+ReLU -> A planes
//                   blocks [4096, 4096+WB2) = fc1 weight split (grid-stride)
// ============================================================================
__global__ __launch_bounds__(256) void feat_kernel(
    const float* __restrict__ data,
    const float* __restrict__ bn_gamma, const float* __restrict__ bn_beta,
    const float* __restrict__ bn_mean, const float* __restrict__ bn_var,
    const float* __restrict__ conv_w, const float* __restrict__ conv_b,
    const float* __restrict__ fc1_w)
{
    const int tid = threadIdx.x;

    if (blockIdx.x >= N_SAMP) {
        // ---- weight-split role: grid-stride ----
        const size_t stride = (size_t)WB2 * 256;
        const size_t total = (size_t)N1 * K1 / 4;
        for (size_t t = (size_t)(blockIdx.x - N_SAMP) * 256 + tid; t < total; t += stride) {
            const size_t i = t * 4;
            float4 v = *(const float4*)(fc1_w + i);
            __half w1x = __float2half_rn(v.x);
            __half w1y = __float2half_rn(v.y);
            __half w1z = __float2half_rn(v.z);
            __half w1w = __float2half_rn(v.w);
            ushort4 h1, h2;
            h1.x = __half_as_ushort(w1x);
            h1.y = __half_as_ushort(w1y);
            h1.z = __half_as_ushort(w1z);
            h1.w = __half_as_ushort(w1w);
            h2.x = __half_as_ushort(__float2half_rn((v.x - __half2float(w1x)) * 64.0f));
            h2.y = __half_as_ushort(__float2half_rn((v.y - __half2float(w1y)) * 64.0f));
            h2.z = __half_as_ushort(__float2half_rn((v.z - __half2float(w1z)) * 64.0f));
            h2.w = __half_as_ushort(__float2half_rn((v.w - __half2float(w1w)) * 64.0f));
            *(ushort4*)((unsigned short*)g_W1 + i) = h1;
            *(ushort4*)((unsigned short*)g_W2 + i) = h2;
        }
        return;
    }

    // ---- feature role ----
    __shared__ float sd[Fh * Wd];
    __shared__ float sstd[Fh * NWIN];
    __shared__ float sfeat[HPR * NWIN];
    __shared__ float scw[48];
    __shared__ float scb[16];

    const int n = blockIdx.x;
    const float* dptr = data + (size_t)n * (Fh * Wd);
    for (int i = tid; i < Fh * Wd; i += 256) sd[i] = dptr[i];
    if (tid < 48) scw[tid] = conv_w[tid];
    if (tid >= 64 && tid < 80) scb[tid - 64] = conv_b[tid - 64];
    const float bscale = rsqrtf(bn_var[0] + 1e-5f) * bn_gamma[0];
    const float bshift = bn_beta[0] - bn_mean[0] * bscale;
    __syncthreads();

    if (tid < Fh * NWIN) {
        const int f = tid / NWIN, w = tid % NWIN;
        float* seg = &sd[f * Wd + w * Sw];
        float mean = 0.f;
        #pragma unroll
        for (int s = 0; s < Sw; s++) mean += seg[s];
        mean *= 0.1f;
        float ret = ffill(seg[Sw - 1] / seg[0] - 1.0f);
        float dl = 0.f;
        #pragma unroll
        for (int s = 0; s < Sw; s++) dl += seg[s] * (float)(s + 1);
        dl *= (1.0f / 55.0f);
        float ss = 0.f;
        #pragma unroll
        for (int s = 0; s < Sw; s++) { float sp = seg[s] - mean; seg[s] = sp; ss += sp * sp; }
        const float sdv = sqrtf(ss * (1.0f / 9.0f));
        sstd[tid] = sdv;
        sfeat[(210 + f) * NWIN + w] = ffill(sdv) * bscale + bshift;
        sfeat[(225 + f) * NWIN + w] = ffill(mean / sdv) * bscale + bshift;
        sfeat[(240 + f) * NWIN + w] = ret * bscale + bshift;
        sfeat[(255 + f) * NWIN + w] = ffill(dl) * bscale + bshift;
    }
    __syncthreads();

    for (int idx = tid; idx < Pn * NWIN; idx += 256) {
        const int p = idx / NWIN, w = idx % NWIN;
        int i = 0, rem = p;
        while (rem >= 14 - i) { rem -= 14 - i; i++; }
        const int j = i + 1 + rem;
        const float* si = &sd[i * Wd + w * Sw];
        const float* sj = &sd[j * Wd + w * Sw];
        float dot = 0.f;
        #pragma unroll
        for (int s = 0; s < Sw; s++) dot += si[s] * sj[s];
        const float cov = dot * (1.0f / 9.0f);
        const float corr = ffill(cov / (sstd[i * NWIN + w] * sstd[j * NWIN + w]) * 0.9f);
        sfeat[p * NWIN + w]         = corr * bscale + bshift;
        sfeat[(105 + p) * NWIN + w] = ffill(cov) * bscale + bshift;
    }
    __syncthreads();

    // Conv + ReLU + fp16 split; streaming stores
    __half* p1 = g_A1 + (size_t)n * K1;
    __half* p2 = g_A2 + (size_t)n * K1;
    for (int p = tid; p < 1350; p += 256) {
        const int h = p / 5;
        const int wc = (p - h * 5) * 2;
        const float* fr = &sfeat[h * NWIN + wc];
        const float f0 = fr[0], f1 = fr[1], f2 = fr[2], f3 = fr[3];
        const int base = h * 10 + wc;
        #pragma unroll 4
        for (int o = 0; o < 16; o++) {
            const float c0 = scw[3 * o], c1 = scw[3 * o + 1], c2 = scw[3 * o + 2];
            float v0 = fmaxf(scb[o] + c0 * f0 + c1 * f1 + c2 * f2, 0.f);
            float v1 = fmaxf(scb[o] + c0 * f1 + c1 * f2 + c2 * f3, 0.f);
            const __half a10 = __float2half_rn(v0 * 0.015625f);
            const __half a11 = __float2half_rn(v1 * 0.015625f);
            const __half a20 = __float2half_rn(v0 - 64.0f * __half2float(a10));
            const __half a21 = __float2half_rn(v1 - 64.0f * __half2float(a11));
            const int idx = o * 2700 + base;
            __stcs((__half2*)(p1 + idx), __halves2half2(a10, a11));
            __stcs((__half2*)(p2 + idx), __halves2half2(a20, a21));
        }
    }
}

// ============================================================================
// Kernel 2: fc1 split-fp16 GEMM, split-K over 9 uniform pieces.
// Grid (4 N, 32 M, 9 K) = 1152 identical CTAs, 1/SM -> scheduler fills 148 SMs.
// Each piece: 75 stages of BK=64 over its K range; identical R7 inner loop.
// Piece output: 64*f32acc + f16cross (raw, no bias/relu) -> g_y1s[kp].
// ============================================================================
__global__ __launch_bounds__(512) void fc1_mma()
{
    extern __shared__ __align__(1024) char smem[];
    const int tid = threadIdx.x;
    const int bx = blockIdx.x;   // N tile 0..3
    const int by = blockIdx.y;   // M tile 0..31
    const int kp = blockIdx.z;   // K piece 0..8
    const int warp = tid >> 5, lane = tid & 31;
    const int wm = warp >> 2;    // 0..3
    const int wn = warp & 3;     // 0..3
    const uint32_t sbase = smem_u32(smem);

    const __half* gp0 = g_A1 + (size_t)(by * 128) * K1;
    const __half* gp1 = g_A2 + (size_t)(by * 128) * K1;
    const __half* gp2 = g_W1 + (size_t)(bx * 128) * K1;
    const __half* gp3 = g_W2 + (size_t)(bx * 128) * K1;
    const int kbeg = kp * PSTG;

    auto issue_stage = [&](int kt, int slot) {
        const int k0 = kt * BK;
        const uint32_t sb = sbase + (uint32_t)slot * 65536u;
        #pragma unroll
        for (int p = 0; p < 8; p++) {
            const int plane = p >> 1;
            const int v = tid + ((p & 1) << 9);
            const int row = v >> 3;      // 0..127
            const int c = v & 7;         // 16B chunk
            const __half* g =
                (plane == 0 ? gp0 : plane == 1 ? gp1 : plane == 2 ? gp2 : gp3)
                + (size_t)row * K1 + k0 + c * 8;
            const uint32_t sa = sb + (uint32_t)plane * 16384u
                              + SWZ((uint32_t)(row * 128 + c * 16));
            asm volatile("cp.async.cg.shared.global [%0], [%1], 16;"
                         :: "r"(sa), "l"(g));
        }
        asm volatile("cp.async.commit_group;");
    };

    issue_stage(kbeg + 0, 0);
    issue_stage(kbeg + 1, 1);

    float acc[2][4][4];
    uint32_t hacc[2][4][2];
    #pragma unroll
    for (int i = 0; i < 2; i++)
        #pragma unroll
        for (int j = 0; j < 4; j++) {
            #pragma unroll
            for (int q = 0; q < 4; q++) acc[i][j][q] = 0.f;
            hacc[i][j][0] = 0u; hacc[i][j][1] = 0u;
        }

    const uint32_t a_row_off = (uint32_t)((wm * 32 + (lane & 15)) * 128);
    const uint32_t a_k_off   = (uint32_t)((lane >> 4) << 4);
    const uint32_t b_row_off = (uint32_t)((wn * 32 + ((lane >> 4) << 3) + (lane & 7)) * 128);
    const uint32_t b_k_off   = (uint32_t)(((lane >> 3) & 1) << 4);

    for (int it = 0; it < PSTG; it++) {
        asm volatile("cp.async.wait_group 1;");
        __syncthreads();
        if (it + 2 < PSTG) issue_stage(kbeg + it + 2, (it + 2) % STAGES);
        else asm volatile("cp.async.commit_group;");

        const uint32_t sb = sbase + (uint32_t)(it % STAGES) * 65536u;
        #pragma unroll
        for (int s = 0; s < 4; s++) {
            uint32_t a1f[2][4], a2f[2][4];
            #pragma unroll
            for (int mt = 0; mt < 2; mt++) {
                const uint32_t off = a_row_off + mt * 2048 + s * 32 + a_k_off;
                ldsm4(a1f[mt], sb + SWZ(off));
                ldsm4(a2f[mt], sb + 16384u + SWZ(off));
            }
            uint32_t w1f[2][4], w2f[2][4];
            #pragma unroll
            for (int q = 0; q < 2; q++) {
                const uint32_t off = b_row_off + q * 2048 + s * 32 + b_k_off;
                ldsm4(w1f[q], sb + 32768u + SWZ(off));
                ldsm4(w2f[q], sb + 49152u + SWZ(off));
            }
            #pragma unroll
            for (int mt = 0; mt < 2; mt++)
                #pragma unroll
                for (int nt = 0; nt < 4; nt++)
                    hmma_f32(acc[mt][nt], a1f[mt], &w1f[nt >> 1][(nt & 1) << 1]);
            #pragma unroll
            for (int mt = 0; mt < 2; mt++)
                #pragma unroll
                for (int nt = 0; nt < 4; nt++)
                    hmma_f16(hacc[mt][nt], a1f[mt], &w2f[nt >> 1][(nt & 1) << 1]);
            #pragma unroll
            for (int mt = 0; mt < 2; mt++)
                #pragma unroll
                for (int nt = 0; nt < 4; nt++)
                    hmma_f16(hacc[mt][nt], a2f[mt], &w1f[nt >> 1][(nt & 1) << 1]);
        }
    }

    // epilogue: raw partial = 64*main + cross -> piece slice (no bias/relu)
    float* ybase = g_y1s + (size_t)kp * N_SAMP * N1;
    #pragma unroll
    for (int mt = 0; mt < 2; mt++) {
        const int r0 = by * 128 + wm * 32 + mt * 16 + (lane >> 2);
        #pragma unroll
        for (int nt = 0; nt < 4; nt++) {
            const int c = bx * 128 + wn * 32 + nt * 8 + ((lane & 3) << 1);
            float2 c0 = __half22float2(*(half2*)&hacc[mt][nt][0]);
            float2 c1 = __half22float2(*(half2*)&hacc[mt][nt][1]);
            float2 v0, v1;
            v0.x = 64.0f * acc[mt][nt][0] + c0.x;
            v0.y = 64.0f * acc[mt][nt][1] + c0.y;
            v1.x = 64.0f * acc[mt][nt][2] + c1.x;
            v1.y = 64.0f * acc[mt][nt][3] + c1.y;
            *(float2*)(ybase + (size_t)r0 * N1 + c) = v0;
            *(float2*)(ybase + (size_t)(r0 + 8) * N1 + c) = v1;
        }
    }
}

// ============================================================================
// Kernel 3: fused fc2(sigmoid) + fc3 -- 256 blocks of 16 rows.
// A-load sums the 9 split-K slices, adds fc1 bias, applies ReLU.
// ============================================================================
__global__ __launch_bounds__(256) void fc23_kernel(
    const float* __restrict__ b1,
    const float* __restrict__ w2, const float* __restrict__ b2,
    const float* __restrict__ w3, const float* __restrict__ b3,
    float* __restrict__ out)
{
    __shared__ float As[32][16];
    __shared__ float Bs[32][128];
    __shared__ float sbuf[16][128];
    __shared__ float sw3[128];

    const int tid = threadIdx.x;
    const int mb = blockIdx.x;
    if (tid < 128) sw3[tid] = w3[tid];
    const int tm = tid >> 5;
    const int tn = tid & 31;

    float acc[2][4] = {};
    for (int kt = 0; kt < 16; kt++) {
        const int k0 = kt * 32;
        if (tid < 128) {
            const int row = tid >> 3, kq = (tid & 7) << 2;
            const size_t off = (size_t)(mb * 16 + row) * N1 + k0 + kq;
            float4 a = *(const float4*)(g_y1s + off);
            #pragma unroll
            for (int s = 1; s < KSPLIT; s++) {
                float4 t = *(const float4*)(g_y1s + (size_t)s * N_SAMP * N1 + off);
                a.x += t.x; a.y += t.y; a.z += t.z; a.w += t.w;
            }
            a.x = fmaxf(a.x + b1[k0 + kq + 0], 0.f);
            a.y = fmaxf(a.y + b1[k0 + kq + 1], 0.f);
            a.z = fmaxf(a.z + b1[k0 + kq + 2], 0.f);
            a.w = fmaxf(a.w + b1[k0 + kq + 3], 0.f);
            As[kq + 0][row] = a.x; As[kq + 1][row] = a.y;
            As[kq + 2][row] = a.z; As[kq + 3][row] = a.w;
        }
        #pragma unroll
        for (int q = 0; q < 4; q++) {
            const int v = tid + q * 256;
            const int row = v >> 3, kq = (v & 7) << 2;
            float4 b = *(const float4*)(w2 + (size_t)row * N1 + k0 + kq);
            Bs[kq + 0][row] = b.x; Bs[kq + 1][row] = b.y;
            Bs[kq + 2][row] = b.z; Bs[kq + 3][row] = b.w;
        }
        __syncthreads();
        #pragma unroll
        for (int k = 0; k < 32; k++) {
            float ra[2], rb[4];
            ra[0] = As[k][tm * 2];
            ra[1] = As[k][tm * 2 + 1];
            *(float4*)rb = *(const float4*)&Bs[k][tn * 4];
            #pragma unroll
            for (int i = 0; i < 2; i++)
                #pragma unroll
                for (int j = 0; j < 4; j++) acc[i][j] += ra[i] * rb[j];
        }
        __syncthreads();
    }

    #pragma unroll
    for (int i = 0; i < 2; i++)
        #pragma unroll
        for (int j = 0; j < 4; j++) {
            const float v = acc[i][j] + b2[tn * 4 + j];
            sbuf[tm * 2 + i][tn * 4 + j] = 1.0f / (1.0f + expf(-v));
        }
    __syncthreads();

    #pragma unroll
    for (int r = 0; r < 2; r++) {
        const int row = tm * 2 + r;
        float s = sbuf[row][tn] * sw3[tn] + sbuf[row][tn + 32] * sw3[tn + 32]
                + sbuf[row][tn + 64] * sw3[tn + 64] + sbuf[row][tn + 96] * sw3[tn + 96];
        #pragma unroll
        for (int o = 16; o; o >>= 1) s += __shfl_down_sync(0xffffffffu, s, o);
        if (tn == 0) out[mb * 16 + row] = s + b3[0];
    }
}

// ============================================================================
extern "C" void kernel_launch(void* const* d_in, const int* in_sizes, int n_in,
                              void* d_out, int out_size) {
    const float* data   = (const float*)d_in[0];
    const float* gamma  = (const float*)d_in[1];
    const float* beta   = (const float*)d_in[2];
    const float* mean   = (const float*)d_in[3];
    const float* var    = (const float*)d_in[4];
    const float* conv_w = (const float*)d_in[5];
    const float* conv_b = (const float*)d_in[6];
    const float* fc1_w  = (const float*)d_in[7];
    const float* fc1_b  = (const float*)d_in[8];
    const float* fc2_w  = (const float*)d_in[9];
    const float* fc2_b  = (const float*)d_in[10];
    const float* fc3_w  = (const float*)d_in[11];
    const float* fc3_b  = (const float*)d_in[12];
    float* out = (float*)d_out;

    const int smem_sz = STAGES * 4 * 16384;  // 196608
    cudaFuncSetAttribute(fc1_mma, cudaFuncAttributeMaxDynamicSharedMemorySize, smem_sz);

    feat_kernel<<<N_SAMP + WB2, 256>>>(data, gamma, beta, mean, var,
                                       conv_w, conv_b, fc1_w);
    dim3 g1(4, 32, KSPLIT);
    fc1_mma<<<g1, 512, smem_sz>>>();
    fc23_kernel<<<256, 256>>>(fc1_b, fc2_w, fc2_b, fc3_w, fc3_b, out);
}